// round 7
// baseline (speedup 1.0000x reference)
#include <cuda_runtime.h>

// SelfAttention_61804579389661 — GB300 sm_103a — Round 7
//
// Algebraic simplification: softmax over a size-1 axis is identically 1.0,
// so attention == 1 and context[b,u] = sum_s hidden_states[b,s,u].
//
// R7: R1's contiguous streaming pattern (each block reads 128 whole 4KB rows
// = 512KB contiguous; measured ~6.6 TB/s vs 6.31 TB/s for the strided
// U-chunk pattern) fused into ONE kernel via a last-block-per-b reduction.
// R2's failure is fixed: __syncthreads() BEFORE tid0's arrival atomic (all
// warps' partial stores must precede the signal), plus writer-side
// __threadfence() (release) and reader-side __threadfence() (acquire).
// Reduction order is fixed -> deterministic across replays.
//
// Output layout (out_size = 98304 fp32):
//   [0      .. 32767 ]  context   (B=32, U=1024)
//   [32768  .. 98303 ]  attention (B=32, S=2048, 1) == 1.0f

#define BB 32
#define SS 2048
#define UU 1024
#define U4 (UU / 4)            // 256 float4 per row
#define NSPLIT 16
#define SCHUNK (SS / NSPLIT)   // 128 contiguous rows per block

// Scratch (device globals — no allocation). g_count is reset by the last
// block each call, so graph replays stay correct.
__device__ float4       g_partial[BB * NSPLIT * U4];   // 2 MiB
__device__ unsigned int g_count[BB];

__global__ void __launch_bounds__(256) fused_kernel(const float4* __restrict__ hs,
                                                    float* __restrict__ out) {
    const int b  = blockIdx.x;   // 0..31
    const int sp = blockIdx.y;   // 0..15
    const int t  = threadIdx.x;  // 0..255 -> float4 column within the row

    // ---- stream 128 contiguous 4KB rows: hs[b, sp*128 .. sp*128+127, :] ----
    const float4* __restrict__ row =
        hs + ((size_t)b * SS + (size_t)sp * SCHUNK) * U4 + t;

    float4 acc = make_float4(0.f, 0.f, 0.f, 0.f);
#pragma unroll 8
    for (int s = 0; s < SCHUNK; ++s) {
        float4 v = __ldcs(row + (size_t)s * U4);
        acc.x += v.x; acc.y += v.y; acc.z += v.z; acc.w += v.w;
    }
    g_partial[(b * NSPLIT + sp) * U4 + t] = acc;

    // ---- ones: attention region, 32 float4 per block, disjoint slices ----
    if (t < 32) {
        float4* ones = (float4*)(out + BB * UU);
        ones[(b * NSPLIT + sp) * 32 + t] = make_float4(1.f, 1.f, 1.f, 1.f);
    }

    // ---- signal arrival: ALL partial stores first, then release+atomic ----
    __threadfence();                       // release: partials visible device-wide
    __syncthreads();                       // ALL warps stored before tid0 signals
    __shared__ unsigned int prev_s;
    if (t == 0) prev_s = atomicAdd(&g_count[b], 1u);
    __syncthreads();

    if (prev_s == NSPLIT - 1) {
        __threadfence();                   // acquire: see all 16 partials
        const float4* __restrict__ p = g_partial + b * NSPLIT * U4 + t;
        float4 r = make_float4(0.f, 0.f, 0.f, 0.f);
#pragma unroll
        for (int k = 0; k < NSPLIT; ++k) { // fixed order -> deterministic
            float4 v = p[(size_t)k * U4];
            r.x += v.x; r.y += v.y; r.z += v.z; r.w += v.w;
        }
        ((float4*)out)[b * U4 + t] = r;

        if (t == 0) g_count[b] = 0;        // reset for next graph replay
    }
}

extern "C" void kernel_launch(void* const* d_in, const int* in_sizes, int n_in,
                              void* d_out, int out_size) {
    // Inputs: [0]=s_prev, [1]=hidden_states, [2]=Ww, [3]=Wb, [4]=Uw, [5]=Ub,
    //         [6]=Vw, [7]=Vb. Only hidden_states is live.
    const float4* hs = (const float4*)d_in[1];
    float* out = (float*)d_out;

    dim3 grid(BB, NSPLIT);
    fused_kernel<<<grid, 256>>>(hs, out);
}

// round 8
// speedup vs baseline: 1.0041x; 1.0041x over previous
#include <cuda_runtime.h>

// SelfAttention_61804579389661 — GB300 sm_103a — Round 8
//
// Algebraic simplification: softmax over a size-1 axis is identically 1.0,
// so attention == 1 and context[b,u] = sum_s hidden_states[b,s,u].
//
// R8: orthogonal experiment — contiguous streaming (R7's 512KB/block, whole
// 4KB rows) AT high occupancy (512 threads/block, 8192 warps ~86% occ,
// which R7 lacked). Threads cover 2 rows x 256 float4-cols per iteration
// (8KB contiguous). Row-pair halves combined in smem (fixed order), then
// last-block-per-b reduce (release/acquire fences + syncthreads-before-
// signal, the R7-correct protocol). No __ldcs this time.
//
// Output layout (out_size = 98304 fp32):
//   [0      .. 32767 ]  context   (B=32, U=1024)
//   [32768  .. 98303 ]  attention (B=32, S=2048, 1) == 1.0f

#define BB 32
#define SS 2048
#define UU 1024
#define U4 (UU / 4)            // 256 float4 per row
#define NSPLIT 16
#define SCHUNK (SS / NSPLIT)   // 128 contiguous rows per block
#define NT 512

// Scratch (device globals — no allocation). g_count reset by last block
// each call -> graph-replay safe.
__device__ float4       g_partial[BB * NSPLIT * U4];   // 2 MiB
__device__ unsigned int g_count[BB];

__global__ void __launch_bounds__(NT) fused_kernel(const float4* __restrict__ hs,
                                                   float* __restrict__ out) {
    const int b  = blockIdx.x;   // 0..31
    const int sp = blockIdx.y;   // 0..15
    const int t  = threadIdx.x;  // 0..511

    const int r   = t >> 8;      // 0..1   -> row within pair
    const int col = t & 255;     // 0..255 -> float4 column

    // ---- stream 128 contiguous rows as 64 x 8KB steps ----
    const float4* __restrict__ base =
        hs + ((size_t)b * SS + (size_t)sp * SCHUNK + r) * U4 + col;

    float4 acc = make_float4(0.f, 0.f, 0.f, 0.f);
#pragma unroll 8
    for (int s = 0; s < SCHUNK / 2; ++s) {              // 64 iters, 2 rows each
        float4 v = base[(size_t)s * 2 * U4];
        acc.x += v.x; acc.y += v.y; acc.z += v.z; acc.w += v.w;
    }

    // ---- combine the two row-halves per column (fixed order) ----
    __shared__ float4 smem[NT];
    smem[t] = acc;
    __syncthreads();
    if (t < U4) {
        float4 hi = smem[t + U4];
        acc = smem[t];
        acc.x += hi.x; acc.y += hi.y; acc.z += hi.z; acc.w += hi.w;
        g_partial[(b * NSPLIT + sp) * U4 + t] = acc;
    }

    // ---- ones: attention region, 32 float4 per block (threads 256..287) ----
    if (t >= 256 && t < 288) {
        float4* ones = (float4*)(out + BB * UU);
        ones[(b * NSPLIT + sp) * 32 + (t - 256)] = make_float4(1.f, 1.f, 1.f, 1.f);
    }

    // ---- signal arrival: partial stores first, then release + atomic ----
    __threadfence();                       // release partials device-wide
    __syncthreads();                       // all warps stored before signal
    __shared__ unsigned int prev_s;
    if (t == 0) prev_s = atomicAdd(&g_count[b], 1u);
    __syncthreads();

    if (prev_s == NSPLIT - 1) {
        __threadfence();                   // acquire: see all 16 partials
        if (t < U4) {
            const float4* __restrict__ p = g_partial + b * NSPLIT * U4 + t;
            float4 rr = make_float4(0.f, 0.f, 0.f, 0.f);
#pragma unroll
            for (int k = 0; k < NSPLIT; ++k) {          // fixed order
                float4 v = p[(size_t)k * U4];
                rr.x += v.x; rr.y += v.y; rr.z += v.z; rr.w += v.w;
            }
            ((float4*)out)[b * U4 + t] = rr;
        }
        if (t == 0) g_count[b] = 0;        // reset for next graph replay
    }
}

extern "C" void kernel_launch(void* const* d_in, const int* in_sizes, int n_in,
                              void* d_out, int out_size) {
    // Inputs: [0]=s_prev, [1]=hidden_states, [2]=Ww, [3]=Wb, [4]=Uw, [5]=Ub,
    //         [6]=Vw, [7]=Vb. Only hidden_states is live.
    const float4* hs = (const float4*)d_in[1];
    float* out = (float*)d_out;

    dim3 grid(BB, NSPLIT);
    fused_kernel<<<grid, NT>>>(hs, out);
}

// round 9
// speedup vs baseline: 1.0811x; 1.0768x over previous
#include <cuda_runtime.h>

// SelfAttention_61804579389661 — GB300 sm_103a — Round 9 (final)
//
// Algebraic simplification: softmax over a size-1 axis is identically 1.0,
// so attention == 1 and context[b,u] = sum_s hidden_states[b,s,u]. The
// entire tanh/GEMM pipeline in the reference is dead code.
//
// Converged design (evidence across R3-R8):
//  - strided U-chunk decomposition (6314 GB/s) beats contiguous-per-block
//    (5976-6004 GB/s) — measured both at high and low occupancy;
//  - zero cross-block communication (last-block-reduce tails cost ~2 us);
//  - 512 threads/block -> 8192 warps, ~86% occ, single wave;
//  - plain loads (__ldcs never helped; hand-batched unrolls regressed);
//  - all-ones attention written in the epilogue of the same launch.
// Kernel runs at ~98.7% of the measured 6.3 TB/s streaming-read ceiling.
//
// Output layout (out_size = 98304 fp32):
//   [0      .. 32767 ]  context   (B=32, U=1024)
//   [32768  .. 98303 ]  attention (B=32, S=2048, 1) == 1.0f

#define BB 32
#define SS 2048
#define UU 1024
#define U4 (UU / 4)        // 256 float4 per row
#define NCHUNK 16          // U-chunks per batch row
#define C4 (U4 / NCHUNK)   // 16 float4 lanes per chunk
#define NT 512             // threads per block
#define SPHASE (NT / C4)   // 32 s-strides per block

__global__ void __launch_bounds__(NT) fused_kernel(const float4* __restrict__ hs,
                                                   float* __restrict__ out) {
    const int b = blockIdx.x;   // 0..31
    const int y = blockIdx.y;   // 0..15
    const int t = threadIdx.x;  // 0..511

    // ---- block (b, y): sum hs[b, :, y*64 : y*64+64] over all S ----
    const int lane = t & (C4 - 1);      // 0..15 -> float4 column in chunk
    const int srow = t >> 4;            // 0..31 -> starting s, stride 32

    const float4* __restrict__ base =
        hs + ((size_t)b * SS + srow) * U4 + y * C4 + lane;

    float4 acc = make_float4(0.f, 0.f, 0.f, 0.f);
#pragma unroll 8
    for (int s = 0; s < SS / SPHASE; ++s) {             // 64 iters, stride 32 rows
        float4 v = base[(size_t)s * SPHASE * U4];
        acc.x += v.x; acc.y += v.y; acc.z += v.z; acc.w += v.w;
    }

    // ---- deterministic in-block reduction of the 32 s-phases ----
    __shared__ float4 smem[NT];
    smem[t] = acc;
    __syncthreads();

    if (t < C4) {
        float4 r = make_float4(0.f, 0.f, 0.f, 0.f);
#pragma unroll
        for (int k = 0; k < SPHASE; ++k) {              // fixed order
            float4 v = smem[k * C4 + t];
            r.x += v.x; r.y += v.y; r.z += v.z; r.w += v.w;
        }
        ((float4*)out)[b * U4 + y * C4 + t] = r;
    }

    // ---- epilogue: attention region = 1.0, spread over all 512 blocks ----
    // 16384 float4 total / 512 blocks = 32 float4 per block (threads 32..63,
    // disjoint from the context-writing threads 0..15).
    if (t >= 32 && t < 64) {
        float4* ones = (float4*)(out + BB * UU);
        ones[(b * NCHUNK + y) * 32 + (t - 32)] = make_float4(1.f, 1.f, 1.f, 1.f);
    }
}

extern "C" void kernel_launch(void* const* d_in, const int* in_sizes, int n_in,
                              void* d_out, int out_size) {
    // Inputs: [0]=s_prev, [1]=hidden_states, [2]=Ww, [3]=Wb, [4]=Uw, [5]=Ub,
    //         [6]=Vw, [7]=Vb. Only hidden_states is live.
    const float4* hs = (const float4*)d_in[1];
    float* out = (float*)d_out;

    dim3 grid(BB, NCHUNK);
    fused_kernel<<<grid, NT>>>(hs, out);
}

// round 10
// speedup vs baseline: 1.0819x; 1.0007x over previous
#include <cuda_runtime.h>

// SelfAttention_61804579389661 — GB300 sm_103a — Round 10
//
// Algebraic simplification: softmax over a size-1 axis is identically 1.0,
// so attention == 1 and context[b,u] = sum_s hidden_states[b,s,u]. The
// entire tanh/GEMM pipeline in the reference is dead code.
//
// Converged design (evidence R3-R9):
//  - strided U-chunk decomposition (6.26-6.34 TB/s) beats contiguous-per-
//    block (5.98-6.0 TB/s), at both high and low occupancy;
//  - zero cross-block communication (last-block-reduce tails cost ~2 us);
//  - 512 threads/block, 8192 warps, single wave;
//  - plain loads; manual load batching regresses (R5); __ldcs neutral (R9).
// R10: only change vs R6 = #pragma unroll 8 -> 16 (ptxas-scheduled deeper
// LDG batching; last untested knob in the winning family).
//
// Output layout (out_size = 98304 fp32):
//   [0      .. 32767 ]  context   (B=32, U=1024)
//   [32768  .. 98303 ]  attention (B=32, S=2048, 1) == 1.0f

#define BB 32
#define SS 2048
#define UU 1024
#define U4 (UU / 4)        // 256 float4 per row
#define NCHUNK 16          // U-chunks per batch row
#define C4 (U4 / NCHUNK)   // 16 float4 lanes per chunk
#define NT 512             // threads per block
#define SPHASE (NT / C4)   // 32 s-strides per block

__global__ void __launch_bounds__(NT) fused_kernel(const float4* __restrict__ hs,
                                                   float* __restrict__ out) {
    const int b = blockIdx.x;   // 0..31
    const int y = blockIdx.y;   // 0..15
    const int t = threadIdx.x;  // 0..511

    // ---- block (b, y): sum hs[b, :, y*64 : y*64+64] over all S ----
    const int lane = t & (C4 - 1);      // 0..15 -> float4 column in chunk
    const int srow = t >> 4;            // 0..31 -> starting s, stride 32

    const float4* __restrict__ base =
        hs + ((size_t)b * SS + srow) * U4 + y * C4 + lane;

    float4 acc = make_float4(0.f, 0.f, 0.f, 0.f);
#pragma unroll 16
    for (int s = 0; s < SS / SPHASE; ++s) {             // 64 iters, stride 32 rows
        float4 v = base[(size_t)s * SPHASE * U4];
        acc.x += v.x; acc.y += v.y; acc.z += v.z; acc.w += v.w;
    }

    // ---- deterministic in-block reduction of the 32 s-phases ----
    __shared__ float4 smem[NT];
    smem[t] = acc;
    __syncthreads();

    if (t < C4) {
        float4 r = make_float4(0.f, 0.f, 0.f, 0.f);
#pragma unroll
        for (int k = 0; k < SPHASE; ++k) {              // fixed order
            float4 v = smem[k * C4 + t];
            r.x += v.x; r.y += v.y; r.z += v.z; r.w += v.w;
        }
        ((float4*)out)[b * U4 + y * C4 + t] = r;
    }

    // ---- epilogue: attention region = 1.0, spread over all 512 blocks ----
    // 16384 float4 total / 512 blocks = 32 float4 per block (threads 32..63,
    // disjoint from the context-writing threads 0..15).
    if (t >= 32 && t < 64) {
        float4* ones = (float4*)(out + BB * UU);
        ones[(b * NCHUNK + y) * 32 + (t - 32)] = make_float4(1.f, 1.f, 1.f, 1.f);
    }
}

extern "C" void kernel_launch(void* const* d_in, const int* in_sizes, int n_in,
                              void* d_out, int out_size) {
    // Inputs: [0]=s_prev, [1]=hidden_states, [2]=Ww, [3]=Wb, [4]=Uw, [5]=Ub,
    //         [6]=Vw, [7]=Vb. Only hidden_states is live.
    const float4* hs = (const float4*)d_in[1];
    float* out = (float*)d_out;

    dim3 grid(BB, NCHUNK);
    fused_kernel<<<grid, NT>>>(hs, out);
}